// round 14
// baseline (speedup 1.0000x reference)
#include <cuda_runtime.h>
#include <cstdint>

// Fused 3x3 dilate (max) + erode (min), fp32, (8,32,512,512) NCHW.
// Border: reduce over valid pixels only (replication == +/-inf pad).
// Output: [dilated | eroded], each 67108864 floats.
//
// R14 FINAL (converged): best-measured configuration, identical to R6/R13.
//   Roofline closure: six structural variants (chunk 8/16 rows, ring depth
//   2-4, STG.cs vs bulk-TMA stores, occ 12-57%) all saturate at
//   6.2-6.3 TB/s = LTS cap (~6.9 TB/s) minus mixed 1R:2W turnaround, with
//   DRAM traffic at the 768MB compulsory floor. Inter-variant deltas are
//   within +/-1.5us run noise; this config had the best kernel time.
// Structure:
//  - Non-persistent; each block = two consecutive 8-row chunks of one
//    image. Both 20KB cp.async.bulk reads issued at block start into two
//    static smem stages (41KB -> 5 blocks/SM; ~200KB/SM reads in flight
//    at launch, sustained by work-queue block churn).
//  - Compute: rolling 3-row register window over smem rows; true left/
//    right neighbors read from smem; out-of-range neighbors replaced by
//    replication (idempotent for min/max -> no infinity paths).
//  - Streaming float4 stores (outputs never re-read).

#define W 512
#define H 512
#define ROWS_OUT 8
#define ROWS_IN  10                     // ROWS_OUT + 2 halo
#define THREADS 128
#define CPB 2                           // chunks per block
#define STAGE_BYTES (ROWS_IN * W * 4)   // 20480

__device__ __forceinline__ void stcs4(float* p, float4 v) {
    asm volatile("st.global.cs.v4.f32 [%0], {%1,%2,%3,%4};"
                 :: "l"(p), "f"(v.x), "f"(v.y), "f"(v.z), "f"(v.w) : "memory");
}

__device__ __forceinline__ void mbar_wait_parity0(uint32_t mbar) {
    asm volatile(
        "{\n\t"
        ".reg .pred P;\n\t"
        "WAIT_%=:\n\t"
        "mbarrier.try_wait.parity.shared.b64 P, [%0], 0, 10000000;\n\t"
        "@P bra.uni DONE_%=;\n\t"
        "bra.uni WAIT_%=;\n\t"
        "DONE_%=:\n\t"
        "}"
        :: "r"(mbar) : "memory");
}

__device__ __forceinline__ void bulk_copy(uint32_t s_data, const float* src,
                                          uint32_t s_mbar) {
    asm volatile("mbarrier.arrive.expect_tx.shared.b64 _, [%0], %1;"
                 :: "r"(s_mbar), "r"((uint32_t)STAGE_BYTES));
    asm volatile(
        "cp.async.bulk.shared::cluster.global.mbarrier::complete_tx::bytes "
        "[%0], [%1], %2, [%3];"
        :: "r"(s_data), "l"(src), "r"((uint32_t)STAGE_BYTES), "r"(s_mbar)
        : "memory");
}

__device__ __forceinline__ void compute_chunk(const float* __restrict__ buf,
                                              int r0, int y0, int x4,
                                              float* __restrict__ dbase,
                                              float* __restrict__ ebase)
{
    auto read_row = [&](int si, float4& v, float& lv, float& rv) {
        const float* rp = buf + si * W;
        v  = *reinterpret_cast<const float4*>(rp + x4);
        lv = (x4 > 0)     ? rp[x4 - 1] : v.x;   // replicate at image edge
        rv = (x4 + 4 < W) ? rp[x4 + 4] : v.w;
    };

    float4 pv, cv, nv;
    float plv, prv, clv, crv, nlv, nrv;

    int sp = r0 - 1 - y0; if (sp < 0) sp = 0;       // replicate top row
    read_row(sp,      pv, plv, prv);
    read_row(r0 - y0, cv, clv, crv);

    float* drow = dbase + (size_t)r0 * W + x4;
    float* erow = ebase + (size_t)r0 * W + x4;

    #pragma unroll
    for (int i = 0; i < ROWS_OUT; ++i) {
        int sn = r0 + i + 1 - y0;
        if (sn > ROWS_IN - 1) sn = ROWS_IN - 1;     // replicate bottom row
        read_row(sn, nv, nlv, nrv);

        float4 vmn, vmx;
        vmn.x = fminf(pv.x, fminf(cv.x, nv.x));
        vmn.y = fminf(pv.y, fminf(cv.y, nv.y));
        vmn.z = fminf(pv.z, fminf(cv.z, nv.z));
        vmn.w = fminf(pv.w, fminf(cv.w, nv.w));
        vmx.x = fmaxf(pv.x, fmaxf(cv.x, nv.x));
        vmx.y = fmaxf(pv.y, fmaxf(cv.y, nv.y));
        vmx.z = fmaxf(pv.z, fmaxf(cv.z, nv.z));
        vmx.w = fmaxf(pv.w, fmaxf(cv.w, nv.w));

        const float vl_mn = fminf(plv, fminf(clv, nlv));
        const float vl_mx = fmaxf(plv, fmaxf(clv, nlv));
        const float vr_mn = fminf(prv, fminf(crv, nrv));
        const float vr_mx = fmaxf(prv, fmaxf(crv, nrv));

        float4 omin, omax;
        omin.x = fminf(vl_mn, fminf(vmn.x, vmn.y));
        omin.y = fminf(vmn.x, fminf(vmn.y, vmn.z));
        omin.z = fminf(vmn.y, fminf(vmn.z, vmn.w));
        omin.w = fminf(vmn.z, fminf(vmn.w, vr_mn));

        omax.x = fmaxf(vl_mx, fmaxf(vmx.x, vmx.y));
        omax.y = fmaxf(vmx.x, fmaxf(vmx.y, vmx.z));
        omax.z = fmaxf(vmx.y, fmaxf(vmx.z, vmx.w));
        omax.w = fmaxf(vmx.z, fmaxf(vmx.w, vr_mx));

        stcs4(drow, omax);
        stcs4(erow, omin);
        drow += W;
        erow += W;

        pv = cv; cv = nv;
        plv = clv; clv = nlv;
        prv = crv; crv = nrv;
    }
}

__global__ __launch_bounds__(THREADS)
void erode_dilate_kernel(const float* __restrict__ in,
                         float* __restrict__ dil,
                         float* __restrict__ ero)
{
    __shared__ __align__(128) float buf[CPB][ROWS_IN * W];
    __shared__ uint64_t mbar[CPB];

    const int bid = blockIdx.x;
    const int img = bid >> 5;            // 32 block-pairs per image
    const int pr  = bid & 31;
    const int r0a = pr * (ROWS_OUT * CPB);
    const int r0b = r0a + ROWS_OUT;

    int y0a = r0a - 1;
    if (y0a < 0) y0a = 0;
    if (y0a > H - ROWS_IN) y0a = H - ROWS_IN;
    int y0b = r0b - 1;
    if (y0b > H - ROWS_IN) y0b = H - ROWS_IN;

    const int tid = threadIdx.x;
    const int x4  = tid * 4;
    const size_t ibase = (size_t)img * (H * W);
    const float* base  = in  + ibase;
    float*       dbase = dil + ibase;
    float*       ebase = ero + ibase;

    const uint32_t s_buf0 = (uint32_t)__cvta_generic_to_shared(&buf[0][0]);
    const uint32_t s_buf1 = (uint32_t)__cvta_generic_to_shared(&buf[1][0]);
    const uint32_t s_mb0  = (uint32_t)__cvta_generic_to_shared(&mbar[0]);
    const uint32_t s_mb1  = (uint32_t)__cvta_generic_to_shared(&mbar[1]);

    if (tid == 0) {
        asm volatile("mbarrier.init.shared.b64 [%0], 1;" :: "r"(s_mb0));
        asm volatile("mbarrier.init.shared.b64 [%0], 1;" :: "r"(s_mb1));
    }
    __syncthreads();
    if (tid == 0) {
        bulk_copy(s_buf0, base + (size_t)y0a * W, s_mb0);
        bulk_copy(s_buf1, base + (size_t)y0b * W, s_mb1);
    }

    mbar_wait_parity0(s_mb0);
    compute_chunk(&buf[0][0], r0a, y0a, x4, dbase, ebase);

    mbar_wait_parity0(s_mb1);
    compute_chunk(&buf[1][0], r0b, y0b, x4, dbase, ebase);
}

extern "C" void kernel_launch(void* const* d_in, const int* in_sizes, int n_in,
                              void* d_out, int out_size)
{
    const float* x = (const float*)d_in[0];
    const int n = in_sizes[0];                      // 67108864
    const int nimg = n / (H * W);                   // 256

    float* dil = (float*)d_out;
    float* ero = (float*)d_out + n;

    const int nblocks = nimg * (H / (ROWS_OUT * CPB));  // 8192
    erode_dilate_kernel<<<nblocks, THREADS>>>(x, dil, ero);
}

// round 15
// speedup vs baseline: 1.0228x; 1.0228x over previous
#include <cuda_runtime.h>
#include <cstdint>

// Fused 3x3 dilate (max) + erode (min), fp32, (8,32,512,512) NCHW.
// Border: reduce over valid pixels only (replication == +/-inf pad).
// Output: [dilated | eroded], each 67108864 floats.
//
// R15 FINAL: resubmission of the session's e2e-best variant (R8, 124.1us).
//   Roofline closure: all converged variants sit at 6.2-6.3 TB/s =
//   LTS cap (~6.9 TB/s) minus mixed 1R:2W turnaround, DRAM traffic at the
//   768MB compulsory floor; kernel times 118-121us, e2e noise +/-1.2us.
//   This variant is the measured best on the scored (e2e) metric.
// Structure:
//  - Non-persistent, 2 chunks/block; both 20KB cp.async.bulk reads issued
//    at block start.
//  - Outputs staged in smem and written as 16KB contiguous cp.async.bulk
//    bursts (bulk_group), with wait_group.read gating out-buffer reuse.
//  - 74KB dynamic smem -> 3 blocks/SM; grid 8192.

#define W 512
#define H 512
#define ROWS_OUT 8
#define ROWS_IN  10
#define THREADS 128
#define STAGE_FLOATS (ROWS_IN * W)          // 5120
#define OUT_FLOATS   (ROWS_OUT * W)         // 4096
#define STAGE_BYTES  (STAGE_FLOATS * 4)     // 20480
#define OUT_BYTES    (OUT_FLOATS * 4)       // 16384
#define SMEM_TOTAL   ((2 * STAGE_FLOATS + 2 * OUT_FLOATS) * 4 + 64)

extern __shared__ float smem_pool[];

__device__ __forceinline__ void mbar_wait(uint32_t mbar, uint32_t parity) {
    asm volatile(
        "{\n\t"
        ".reg .pred P;\n\t"
        "WAIT_%=:\n\t"
        "mbarrier.try_wait.parity.shared.b64 P, [%0], %1, 10000000;\n\t"
        "@P bra.uni DONE_%=;\n\t"
        "bra.uni WAIT_%=;\n\t"
        "DONE_%=:\n\t"
        "}"
        :: "r"(mbar), "r"(parity) : "memory");
}

__device__ __forceinline__ void bulk_load(uint32_t s_data, const float* src,
                                          uint32_t s_mbar) {
    asm volatile("mbarrier.arrive.expect_tx.shared.b64 _, [%0], %1;"
                 :: "r"(s_mbar), "r"((uint32_t)STAGE_BYTES));
    asm volatile(
        "cp.async.bulk.shared::cluster.global.mbarrier::complete_tx::bytes "
        "[%0], [%1], %2, [%3];"
        :: "r"(s_data), "l"(src), "r"((uint32_t)STAGE_BYTES), "r"(s_mbar)
        : "memory");
}

__device__ __forceinline__ void bulk_store(float* dst, uint32_t s_src) {
    asm volatile(
        "cp.async.bulk.global.shared::cta.bulk_group [%0], [%1], %2;"
        :: "l"(dst), "r"(s_src), "r"((uint32_t)OUT_BYTES) : "memory");
}

__device__ __forceinline__ void compute_chunk(const float* __restrict__ buf,
                                              int r0, int y0, int x4,
                                              float* __restrict__ dout,
                                              float* __restrict__ eout)
{
    auto read_row = [&](int si, float4& v, float& lv, float& rv) {
        const float* rp = buf + si * W;
        v  = *reinterpret_cast<const float4*>(rp + x4);
        lv = (x4 > 0)     ? rp[x4 - 1] : v.x;   // replicate at image edge
        rv = (x4 + 4 < W) ? rp[x4 + 4] : v.w;
    };

    float4 pv, cv, nv;
    float plv, prv, clv, crv, nlv, nrv;

    int sp = r0 - 1 - y0; if (sp < 0) sp = 0;       // replicate top row
    read_row(sp,      pv, plv, prv);
    read_row(r0 - y0, cv, clv, crv);

    #pragma unroll
    for (int i = 0; i < ROWS_OUT; ++i) {
        int sn = r0 + i + 1 - y0;
        if (sn > ROWS_IN - 1) sn = ROWS_IN - 1;     // replicate bottom row
        read_row(sn, nv, nlv, nrv);

        float4 vmn, vmx;
        vmn.x = fminf(pv.x, fminf(cv.x, nv.x));
        vmn.y = fminf(pv.y, fminf(cv.y, nv.y));
        vmn.z = fminf(pv.z, fminf(cv.z, nv.z));
        vmn.w = fminf(pv.w, fminf(cv.w, nv.w));
        vmx.x = fmaxf(pv.x, fmaxf(cv.x, nv.x));
        vmx.y = fmaxf(pv.y, fmaxf(cv.y, nv.y));
        vmx.z = fmaxf(pv.z, fmaxf(cv.z, nv.z));
        vmx.w = fmaxf(pv.w, fmaxf(cv.w, nv.w));

        const float vl_mn = fminf(plv, fminf(clv, nlv));
        const float vl_mx = fmaxf(plv, fmaxf(clv, nlv));
        const float vr_mn = fminf(prv, fminf(crv, nrv));
        const float vr_mx = fmaxf(prv, fmaxf(crv, nrv));

        float4 omin, omax;
        omin.x = fminf(vl_mn, fminf(vmn.x, vmn.y));
        omin.y = fminf(vmn.x, fminf(vmn.y, vmn.z));
        omin.z = fminf(vmn.y, fminf(vmn.z, vmn.w));
        omin.w = fminf(vmn.z, fminf(vmn.w, vr_mn));

        omax.x = fmaxf(vl_mx, fmaxf(vmx.x, vmx.y));
        omax.y = fmaxf(vmx.x, fmaxf(vmx.y, vmx.z));
        omax.z = fmaxf(vmx.y, fmaxf(vmx.z, vmx.w));
        omax.w = fmaxf(vmx.z, fmaxf(vmx.w, vr_mx));

        *reinterpret_cast<float4*>(dout + i * W + x4) = omax;
        *reinterpret_cast<float4*>(eout + i * W + x4) = omin;

        pv = cv; cv = nv;
        plv = clv; clv = nlv;
        prv = crv; crv = nrv;
    }
}

__global__ __launch_bounds__(THREADS)
void erode_dilate_kernel(const float* __restrict__ in,
                         float* __restrict__ dil,
                         float* __restrict__ ero)
{
    float* stage0 = smem_pool;
    float* stage1 = smem_pool + STAGE_FLOATS;
    float* dout   = smem_pool + 2 * STAGE_FLOATS;
    float* eout   = dout + OUT_FLOATS;
    uint64_t* mbar = (uint64_t*)(eout + OUT_FLOATS);

    const int tid = threadIdx.x;
    const int x4  = tid * 4;
    const int bid = blockIdx.x;

    // two consecutive chunks
    const int c0 = 2 * bid;
    const int img = c0 >> 6;
    const int r0a = (c0 & 63) * ROWS_OUT;
    const int r0b = r0a + ROWS_OUT;

    int y0a = r0a - 1;
    if (y0a < 0) y0a = 0;
    if (y0a > H - ROWS_IN) y0a = H - ROWS_IN;
    int y0b = r0b - 1;
    if (y0b > H - ROWS_IN) y0b = H - ROWS_IN;

    const size_t ibase = (size_t)img * (H * W);
    const float* base  = in  + ibase;
    float*       dbase = dil + ibase;
    float*       ebase = ero + ibase;

    const uint32_t s_st0 = (uint32_t)__cvta_generic_to_shared(stage0);
    const uint32_t s_st1 = (uint32_t)__cvta_generic_to_shared(stage1);
    const uint32_t s_do  = (uint32_t)__cvta_generic_to_shared(dout);
    const uint32_t s_eo  = (uint32_t)__cvta_generic_to_shared(eout);
    const uint32_t s_mb0 = (uint32_t)__cvta_generic_to_shared(&mbar[0]);
    const uint32_t s_mb1 = (uint32_t)__cvta_generic_to_shared(&mbar[1]);

    if (tid == 0) {
        asm volatile("mbarrier.init.shared.b64 [%0], 1;" :: "r"(s_mb0));
        asm volatile("mbarrier.init.shared.b64 [%0], 1;" :: "r"(s_mb1));
    }
    __syncthreads();
    if (tid == 0) {
        bulk_load(s_st0, base + (size_t)y0a * W, s_mb0);
        bulk_load(s_st1, base + (size_t)y0b * W, s_mb1);
    }

    // ---- chunk A ----
    mbar_wait(s_mb0, 0);
    compute_chunk(stage0, r0a, y0a, x4, dout, eout);
    __syncthreads();                         // all results in smem
    if (tid == 0) {
        asm volatile("fence.proxy.async.shared::cta;" ::: "memory");
        bulk_store(dbase + (size_t)r0a * W, s_do);
        bulk_store(ebase + (size_t)r0a * W, s_eo);
        asm volatile("cp.async.bulk.commit_group;" ::: "memory");
    }

    // ---- chunk B ----
    mbar_wait(s_mb1, 0);
    if (tid == 0) {
        // wait until chunk A's stores finished READING the out buffers
        asm volatile("cp.async.bulk.wait_group.read 0;" ::: "memory");
    }
    __syncthreads();                         // gate reuse of dout/eout
    compute_chunk(stage1, r0b, y0b, x4, dout, eout);
    __syncthreads();
    if (tid == 0) {
        asm volatile("fence.proxy.async.shared::cta;" ::: "memory");
        bulk_store(dbase + (size_t)r0b * W, s_do);
        bulk_store(ebase + (size_t)r0b * W, s_eo);
        asm volatile("cp.async.bulk.commit_group;" ::: "memory");
        // smem is freed at CTA exit: stores must be fully done
        asm volatile("cp.async.bulk.wait_group 0;" ::: "memory");
    }
}

extern "C" void kernel_launch(void* const* d_in, const int* in_sizes, int n_in,
                              void* d_out, int out_size)
{
    const float* x = (const float*)d_in[0];
    const int n = in_sizes[0];                  // 67108864
    const int nimg = n / (H * W);               // 256

    float* dil = (float*)d_out;
    float* ero = (float*)d_out + n;

    cudaFuncSetAttribute(erode_dilate_kernel,
                         cudaFuncAttributeMaxDynamicSharedMemorySize,
                         SMEM_TOTAL);

    const int nblocks = nimg * (H / (ROWS_OUT * 2));  // 8192
    erode_dilate_kernel<<<nblocks, THREADS, SMEM_TOTAL>>>(x, dil, ero);
}